// round 5
// baseline (speedup 1.0000x reference)
#include <cuda_runtime.h>
#include <cstddef>
#include <cstdint>

#define EMB 384
#define NMAX 50000
#define EMAX 800000

// Scratch (static __device__ arrays; no allocation anywhere)
__device__ float g_bufA[(size_t)NMAX * EMB];
__device__ float g_bufB[(size_t)NMAX * EMB];
__device__ float g_bufC[(size_t)NMAX * EMB];
__device__ float g_dinv[NMAX];
__device__ int   g_deg[NMAX];
__device__ int   g_rowptr[NMAX + 1];
__device__ int   g_cnt[NMAX];
__device__ int   g_csr[EMAX];
__device__ int   g_bsum[1024];

template <int SEL>
__device__ __forceinline__ float* BUF() {
    if constexpr (SEL == 0) return g_bufA;
    else if constexpr (SEL == 1) return g_bufB;
    else return g_bufC;
}

__device__ __forceinline__ float leaky01(float x) { return x > 0.f ? x : 0.01f * x; }

__device__ __forceinline__ uint32_t f2tf(float x) {
    uint32_t u;
    asm("cvt.rna.tf32.f32 %0, %1;" : "=r"(u) : "f"(x));
    return u;
}

__device__ __forceinline__ void cp_async16(void* smem_dst, const void* gsrc, int src_bytes) {
    uint32_t saddr = (uint32_t)__cvta_generic_to_shared(smem_dst);
    asm volatile("cp.async.cg.shared.global [%0], [%1], 16, %2;"
                 :: "r"(saddr), "l"(gsrc), "r"(src_bytes) : "memory");
}
#define CP_COMMIT() asm volatile("cp.async.commit_group;" ::: "memory")
#define CP_WAIT1()  asm volatile("cp.async.wait_group 1;" ::: "memory")
#define CP_WAIT0()  asm volatile("cp.async.wait_group 0;" ::: "memory")

__device__ __forceinline__ void mma_tf32(
    float& c0, float& c1, float& c2, float& c3,
    uint32_t a0, uint32_t a1, uint32_t a2, uint32_t a3,
    uint32_t b0, uint32_t b1)
{
    asm volatile(
        "mma.sync.aligned.m16n8k8.row.col.f32.tf32.tf32.f32 "
        "{%0,%1,%2,%3}, {%4,%5,%6,%7}, {%8,%9}, {%0,%1,%2,%3};"
        : "+f"(c0), "+f"(c1), "+f"(c2), "+f"(c3)
        : "r"(a0), "r"(a1), "r"(a2), "r"(a3), "r"(b0), "r"(b1));
}

// ---------------------------------------------------------------------------
// tf32 tensor-core GEMM, cp.async 3-stage pipeline, one barrier per K-tile.
// C[M,Nc] = act(A[M,K] @ B[K,Nc] + bias). BM=128, BN=64, BK=16.
// 8 warps: 4(m) x 2(n); each warp 32x32 via 2x4 m16n8k8 tiles.
// ---------------------------------------------------------------------------
template <int SRC, int DST, int HAS_BIAS, int ACT>
__global__ void __launch_bounds__(256) tgemm(
    const float* __restrict__ Ain, const float* __restrict__ B,
    const float* __restrict__ bias,
    int M, int K, int Nc, int ldc, int coff)
{
    const float* __restrict__ A;
    if constexpr (SRC < 0) A = Ain; else A = BUF<SRC>();
    float* __restrict__ C = BUF<DST>();

    __shared__ float As[3][128][20];   // row-major [m][k], stride 20
    __shared__ float Bs[3][16][72];    // [k][n], stride 72

    const int tid = threadIdx.x;
    const int lane = tid & 31;
    const int warp = tid >> 5;
    const int warp_m = warp & 3;
    const int warp_n = warp >> 2;
    const int gid = lane >> 2;
    const int tig = lane & 3;

    const int row0 = blockIdx.y * 128;
    const int col0 = blockIdx.x * 64;

    float c[2][4][4];
    #pragma unroll
    for (int i = 0; i < 2; i++)
        #pragma unroll
        for (int j = 0; j < 4; j++)
            #pragma unroll
            for (int q = 0; q < 4; q++) c[i][j][q] = 0.f;

    auto load_tile = [&](int kt, int buf) {
        const int k0 = kt * 16;
        #pragma unroll
        for (int i = 0; i < 2; i++) {
            int seg = tid + i * 256;
            int r = seg >> 2;
            int cf = (seg & 3) * 4;
            int gr = row0 + r;
            int grc = gr < M ? gr : (M - 1);
            cp_async16(&As[buf][r][cf],
                       A + (size_t)grc * K + k0 + cf,
                       gr < M ? 16 : 0);
        }
        {
            int r = tid >> 4;
            int cf = (tid & 15) * 4;
            cp_async16(&Bs[buf][r][cf],
                       B + (size_t)(k0 + r) * Nc + col0 + cf, 16);
        }
    };

    auto compute = [&](int buf) {
        #pragma unroll
        for (int ks = 0; ks < 16; ks += 8) {
            uint32_t af[2][4], bf[4][2];
            #pragma unroll
            for (int tm = 0; tm < 2; tm++) {
                int mrow = warp_m * 32 + tm * 16 + gid;
                af[tm][0] = f2tf(As[buf][mrow][ks + tig]);
                af[tm][1] = f2tf(As[buf][mrow + 8][ks + tig]);
                af[tm][2] = f2tf(As[buf][mrow][ks + tig + 4]);
                af[tm][3] = f2tf(As[buf][mrow + 8][ks + tig + 4]);
            }
            #pragma unroll
            for (int tn = 0; tn < 4; tn++) {
                int ncol = warp_n * 32 + tn * 8 + gid;
                bf[tn][0] = f2tf(Bs[buf][ks + tig][ncol]);
                bf[tn][1] = f2tf(Bs[buf][ks + tig + 4][ncol]);
            }
            #pragma unroll
            for (int tm = 0; tm < 2; tm++)
                #pragma unroll
                for (int tn = 0; tn < 4; tn++)
                    mma_tf32(c[tm][tn][0], c[tm][tn][1], c[tm][tn][2], c[tm][tn][3],
                             af[tm][0], af[tm][1], af[tm][2], af[tm][3],
                             bf[tn][0], bf[tn][1]);
        }
    };

    const int KT = K >> 4;                // >= 2 for all call sites
    load_tile(0, 0); CP_COMMIT();
    load_tile(1, 1); CP_COMMIT();

    for (int kt = 0; kt < KT; kt++) {
        if (kt < KT - 1) CP_WAIT1(); else CP_WAIT0();
        __syncthreads();                  // tile kt visible to all; buf (kt-1)%3 free
        if (kt + 2 < KT) {
            load_tile(kt + 2, (kt + 2) % 3);
            CP_COMMIT();
        }
        compute(kt % 3);
        // no trailing barrier: next iter's barrier protects buffer reuse
        __syncthreads();
    }

    // Epilogue
    #pragma unroll
    for (int tm = 0; tm < 2; tm++) {
        int rbase = row0 + warp_m * 32 + tm * 16 + gid;
        #pragma unroll
        for (int tn = 0; tn < 4; tn++) {
            int gc = col0 + warp_n * 32 + tn * 8 + 2 * tig;
            float bx = 0.f, by = 0.f;
            if (HAS_BIAS) { bx = bias[gc]; by = bias[gc + 1]; }
            #pragma unroll
            for (int half = 0; half < 2; half++) {
                int gr = rbase + half * 8;
                if (gr >= M) continue;
                float v0 = c[tm][tn][half * 2 + 0] + bx;
                float v1 = c[tm][tn][half * 2 + 1] + by;
                if (ACT) { v0 = leaky01(v0); v1 = leaky01(v1); }
                *(float2*)(C + (size_t)gr * ldc + coff + gc) = make_float2(v0, v1);
            }
        }
    }
}

// ---------------------------------------------------------------------------
// num/cat feature linears (K=4, K=3) -> concat columns [128:256), [256:384)
// ---------------------------------------------------------------------------
__global__ void numcat_kernel(
    const float* __restrict__ np_, const float* __restrict__ cp,
    const float* __restrict__ Wn, const float* __restrict__ bn,
    const float* __restrict__ Wc, const float* __restrict__ bc, int N)
{
    int i = blockIdx.x * blockDim.x + threadIdx.x;
    int node = i >> 7;
    int col = i & 127;
    if (node >= N) return;

    float s = bn[col];
    #pragma unroll
    for (int k = 0; k < 4; k++) s += np_[node * 4 + k] * Wn[k * 128 + col];
    g_bufA[(size_t)node * EMB + 128 + col] = leaky01(s);

    float t = bc[col];
    #pragma unroll
    for (int k = 0; k < 3; k++) t += cp[node * 3 + k] * Wc[k * 128 + col];
    g_bufA[(size_t)node * EMB + 256 + col] = leaky01(t);
}

// ---------------------------------------------------------------------------
// Degree / dinv / CSR build (edge_index int32; CSR keyed by dst, stores src)
// ---------------------------------------------------------------------------
__global__ void zero_deg(int N)
{
    int i = blockIdx.x * blockDim.x + threadIdx.x;
    if (i < N) g_deg[i] = 0;
}

__global__ void count_deg(const int* __restrict__ ei, int E)
{
    int e = blockIdx.x * blockDim.x + threadIdx.x;
    if (e < E) atomicAdd(&g_deg[ei[E + e]], 1);
}

// Pass 1: per-block sums of deg (256 elems/block) + dinv
__global__ void scan_pass1(int N)
{
    __shared__ int red[256];
    int t = threadIdx.x;
    int i = blockIdx.x * 256 + t;
    int d = (i < N) ? g_deg[i] : 0;
    if (i < N) g_dinv[i] = rsqrtf((float)d + 1.0f);
    red[t] = d;
    __syncthreads();
    #pragma unroll
    for (int off = 128; off > 0; off >>= 1) {
        if (t < off) red[t] += red[t + off];
        __syncthreads();
    }
    if (t == 0) g_bsum[blockIdx.x] = red[0];
}

// Pass 2: single block exclusive-scans the <=1024 block sums in place
__global__ void __launch_bounds__(1024) scan_pass2(int NB)
{
    __shared__ int s[1024];
    int t = threadIdx.x;
    int v = (t < NB) ? g_bsum[t] : 0;
    s[t] = v;
    __syncthreads();
    #pragma unroll
    for (int off = 1; off < 1024; off <<= 1) {
        int u = (t >= off) ? s[t - off] : 0;
        __syncthreads();
        s[t] += u;
        __syncthreads();
    }
    if (t < NB) g_bsum[t] = s[t] - v;   // exclusive
}

// Pass 3: per-block local exclusive scan + base -> rowptr; zero cnt
__global__ void scan_pass3(int N)
{
    __shared__ int s[256];
    int t = threadIdx.x;
    int i = blockIdx.x * 256 + t;
    int d = (i < N) ? g_deg[i] : 0;
    s[t] = d;
    __syncthreads();
    #pragma unroll
    for (int off = 1; off < 256; off <<= 1) {
        int u = (t >= off) ? s[t - off] : 0;
        __syncthreads();
        s[t] += u;
        __syncthreads();
    }
    int base = g_bsum[blockIdx.x];
    if (i < N) {
        g_rowptr[i] = base + s[t] - d;   // exclusive
        g_cnt[i] = 0;
        if (i == N - 1) g_rowptr[N] = base + s[t];
    }
}

__global__ void fill_csr(const int* __restrict__ ei, int E)
{
    int e = blockIdx.x * blockDim.x + threadIdx.x;
    if (e >= E) return;
    int d = ei[E + e];
    int pos = g_rowptr[d] + atomicAdd(&g_cnt[d], 1);
    g_csr[pos] = ei[e];
}

// ---------------------------------------------------------------------------
// GCN gather: one warp per node. agg[n] = sum_{s in in(n)} xw[s]*dinv[s]*dinv[n]
//                                        + xw[n]*dinv[n]^2 + bias
// ---------------------------------------------------------------------------
__device__ __forceinline__ void fma4(float4& a, const float4 v, float n) {
    a.x = fmaf(v.x, n, a.x);
    a.y = fmaf(v.y, n, a.y);
    a.z = fmaf(v.z, n, a.z);
    a.w = fmaf(v.w, n, a.w);
}

template <int SRC, int DST>
__global__ void gcn_gather(const float* __restrict__ bias, int N)
{
    const float* __restrict__ xw = BUF<SRC>();
    float* __restrict__ agg = BUF<DST>();

    int w = (blockIdx.x * blockDim.x + threadIdx.x) >> 5;
    int lane = threadIdx.x & 31;
    if (w >= N) return;

    float din = g_dinv[w];
    float self = din * din;

    const float4* xr = (const float4*)(xw + (size_t)w * EMB);
    const float4* bi = (const float4*)bias;

    float4 a0 = bi[lane], a1 = bi[lane + 32], a2 = bi[lane + 64];
    fma4(a0, xr[lane], self);
    fma4(a1, xr[lane + 32], self);
    fma4(a2, xr[lane + 64], self);

    int p = g_rowptr[w];
    const int pe = g_rowptr[w + 1];

    for (; p + 1 < pe; p += 2) {
        int s0 = g_csr[p], s1 = g_csr[p + 1];
        float n0 = g_dinv[s0] * din;
        float n1 = g_dinv[s1] * din;
        const float4* x0 = (const float4*)(xw + (size_t)s0 * EMB);
        const float4* x1 = (const float4*)(xw + (size_t)s1 * EMB);
        float4 v00 = x0[lane], v01 = x0[lane + 32], v02 = x0[lane + 64];
        float4 v10 = x1[lane], v11 = x1[lane + 32], v12 = x1[lane + 64];
        fma4(a0, v00, n0); fma4(a1, v01, n0); fma4(a2, v02, n0);
        fma4(a0, v10, n1); fma4(a1, v11, n1); fma4(a2, v12, n1);
    }
    if (p < pe) {
        int s0 = g_csr[p];
        float n0 = g_dinv[s0] * din;
        const float4* x0 = (const float4*)(xw + (size_t)s0 * EMB);
        fma4(a0, x0[lane], n0);
        fma4(a1, x0[lane + 32], n0);
        fma4(a2, x0[lane + 64], n0);
    }

    float4* ar = (float4*)(agg + (size_t)w * EMB);
    ar[lane] = a0;
    ar[lane + 32] = a1;
    ar[lane + 64] = a2;
}

// ---------------------------------------------------------------------------
// Final projection to 2 logits from g_bufA: one warp per node.
// ---------------------------------------------------------------------------
__global__ void out_kernel(
    const float* __restrict__ W, const float* __restrict__ b,
    float* __restrict__ out, int N)
{
    int warp = (blockIdx.x * blockDim.x + threadIdx.x) >> 5;
    int lane = threadIdx.x & 31;
    if (warp >= N) return;

    const float* x = g_bufA + (size_t)warp * EMB;
    float s0 = 0.f, s1 = 0.f;
    #pragma unroll
    for (int it = 0; it < EMB / 32; it++) {
        int j = it * 32 + lane;
        float v = x[j];
        s0 += v * W[j * 2 + 0];
        s1 += v * W[j * 2 + 1];
    }
    #pragma unroll
    for (int o = 16; o > 0; o >>= 1) {
        s0 += __shfl_down_sync(0xFFFFFFFFu, s0, o);
        s1 += __shfl_down_sync(0xFFFFFFFFu, s1, o);
    }
    if (lane == 0) {
        out[(size_t)warp * 2 + 0] = s0 + b[0];
        out[(size_t)warp * 2 + 1] = s1 + b[1];
    }
}

// ---------------------------------------------------------------------------
// Launcher — kernel launches only (graph-capturable, allocation-free)
// ---------------------------------------------------------------------------
extern "C" void kernel_launch(void* const* d_in, const int* in_sizes, int n_in,
                              void* d_out, int out_size)
{
    const float* des = (const float*)d_in[0];
    // d_in[1] = tweet — unused by the reference model
    const float* np_ = (const float*)d_in[2];
    const float* cp  = (const float*)d_in[3];
    const int*   ei  = (const int*)d_in[4];
    const float* W_des = (const float*)d_in[5];  const float* b_des = (const float*)d_in[6];
    const float* W_num = (const float*)d_in[7];  const float* b_num = (const float*)d_in[8];
    const float* W_cat = (const float*)d_in[9];  const float* b_cat = (const float*)d_in[10];
    const float* W_in  = (const float*)d_in[11]; const float* b_in  = (const float*)d_in[12];
    const float* W_g1  = (const float*)d_in[13]; const float* b_g1  = (const float*)d_in[14];
    const float* W_g2  = (const float*)d_in[15]; const float* b_g2  = (const float*)d_in[16];
    const float* W_o1  = (const float*)d_in[17]; const float* b_o1  = (const float*)d_in[18];
    const float* W_o2  = (const float*)d_in[19]; const float* b_o2  = (const float*)d_in[20];

    const int N = in_sizes[0] / 768;
    const int E = in_sizes[4] / 2;

    const int mb = (N + 127) / 128;
    const int NB = (N + 255) / 256;
    const int nwarpgrid = (int)(((size_t)N * 32 + 255) / 256);

    // --- degree / dinv / CSR ---
    zero_deg<<<NB, 256>>>(N);
    count_deg<<<(E + 255) / 256, 256>>>(ei, E);
    scan_pass1<<<NB, 256>>>(N);
    scan_pass2<<<1, 1024>>>(NB);
    scan_pass3<<<NB, 256>>>(N);
    fill_csr<<<(E + 255) / 256, 256>>>(ei, E);

    // --- feature embedding: bufA = concat of 3 leaky-linears ---
    tgemm<-1, 0, 1, 1><<<dim3(2, mb), 256>>>(des, W_des, b_des, N, 768, 128, EMB, 0);
    numcat_kernel<<<(N * 128 + 255) / 256, 256>>>(np_, cp, W_num, b_num, W_cat, b_cat, N);

    // --- input linear: bufB = leaky(bufA @ W_in + b_in) ---
    tgemm<0, 1, 1, 1><<<dim3(6, mb), 256>>>(nullptr, W_in, b_in, N, EMB, EMB, EMB, 0);

    // --- GCN conv 1: bufC = bufB @ W_g1 ; bufA = gather(bufC) + b_g1 ---
    tgemm<1, 2, 0, 0><<<dim3(6, mb), 256>>>(nullptr, W_g1, nullptr, N, EMB, EMB, EMB, 0);
    gcn_gather<2, 0><<<nwarpgrid, 256>>>(b_g1, N);

    // --- GCN conv 2: bufC = bufA @ W_g2 ; bufB = gather(bufC) + b_g2 ---
    tgemm<0, 2, 0, 0><<<dim3(6, mb), 256>>>(nullptr, W_g2, nullptr, N, EMB, EMB, EMB, 0);
    gcn_gather<2, 1><<<nwarpgrid, 256>>>(b_g2, N);

    // --- output head: bufA = leaky(bufB @ W_o1 + b_o1); out = bufA @ W_o2 + b_o2 ---
    tgemm<1, 0, 1, 1><<<dim3(6, mb), 256>>>(nullptr, W_o1, b_o1, N, EMB, EMB, EMB, 0);
    out_kernel<<<nwarpgrid, 256>>>(W_o2, b_o2, (float*)d_out, N);
}

// round 6
// speedup vs baseline: 1.1115x; 1.1115x over previous
#include <cuda_runtime.h>
#include <cstddef>
#include <cstdint>

#define EMB 384
#define NMAX 50000
#define EMAX 800000

// Scratch (static __device__ arrays; no allocation anywhere)
__device__ float g_bufA[(size_t)NMAX * EMB];
__device__ float g_bufB[(size_t)NMAX * EMB];
__device__ float g_bufC[(size_t)NMAX * EMB];
__device__ float g_dinv[NMAX];
__device__ int   g_deg[NMAX];
__device__ int   g_rowptr[NMAX + 1];
__device__ int   g_cnt[NMAX];
__device__ int   g_csr[EMAX];
__device__ int   g_bsum[1024];

template <int SEL>
__device__ __forceinline__ float* BUF() {
    if constexpr (SEL == 0) return g_bufA;
    else if constexpr (SEL == 1) return g_bufB;
    else return g_bufC;
}

__device__ __forceinline__ float leaky01(float x) { return x > 0.f ? x : 0.01f * x; }

__device__ __forceinline__ uint32_t f2tf(float x) {
    uint32_t u;
    asm("cvt.rna.tf32.f32 %0, %1;" : "=r"(u) : "f"(x));
    return u;
}

__device__ __forceinline__ void cp_async16(void* smem_dst, const void* gsrc, int src_bytes) {
    uint32_t saddr = (uint32_t)__cvta_generic_to_shared(smem_dst);
    asm volatile("cp.async.cg.shared.global [%0], [%1], 16, %2;"
                 :: "r"(saddr), "l"(gsrc), "r"(src_bytes) : "memory");
}
#define CP_COMMIT() asm volatile("cp.async.commit_group;" ::: "memory")
#define CP_WAIT1()  asm volatile("cp.async.wait_group 1;" ::: "memory")
#define CP_WAIT0()  asm volatile("cp.async.wait_group 0;" ::: "memory")

__device__ __forceinline__ void mma_tf32(
    float& c0, float& c1, float& c2, float& c3,
    uint32_t a0, uint32_t a1, uint32_t a2, uint32_t a3,
    uint32_t b0, uint32_t b1)
{
    asm volatile(
        "mma.sync.aligned.m16n8k8.row.col.f32.tf32.tf32.f32 "
        "{%0,%1,%2,%3}, {%4,%5,%6,%7}, {%8,%9}, {%0,%1,%2,%3};"
        : "+f"(c0), "+f"(c1), "+f"(c2), "+f"(c3)
        : "r"(a0), "r"(a1), "r"(a2), "r"(a3), "r"(b0), "r"(b1));
}

// ---------------------------------------------------------------------------
// tf32 tensor-core GEMM, cp.async double-buffered (R4-proven version).
// C[M,Nc] = act(A[M,K] @ B[K,Nc] + bias). BM=128, BN=64, BK=16, 2 stages.
// 8 warps: 4(m) x 2(n); each warp 32x32 via 2x4 m16n8k8 tiles.
// ---------------------------------------------------------------------------
template <int SRC, int DST, int HAS_BIAS, int ACT>
__global__ void __launch_bounds__(256) tgemm(
    const float* __restrict__ Ain, const float* __restrict__ B,
    const float* __restrict__ bias,
    int M, int K, int Nc, int ldc, int coff)
{
    const float* __restrict__ A;
    if constexpr (SRC < 0) A = Ain; else A = BUF<SRC>();
    float* __restrict__ C = BUF<DST>();

    __shared__ float As[2][128][20];   // row-major [m][k], stride 20 (conflict-free)
    __shared__ float Bs[2][16][72];    // [k][n], stride 72 (conflict-free)

    const int tid = threadIdx.x;
    const int lane = tid & 31;
    const int warp = tid >> 5;
    const int warp_m = warp & 3;
    const int warp_n = warp >> 2;
    const int gid = lane >> 2;
    const int tig = lane & 3;

    const int row0 = blockIdx.y * 128;
    const int col0 = blockIdx.x * 64;

    float c[2][4][4];
    #pragma unroll
    for (int i = 0; i < 2; i++)
        #pragma unroll
        for (int j = 0; j < 4; j++)
            #pragma unroll
            for (int q = 0; q < 4; q++) c[i][j][q] = 0.f;

    auto load_tile = [&](int kt, int buf) {
        const int k0 = kt * 16;
        #pragma unroll
        for (int i = 0; i < 2; i++) {
            int seg = tid + i * 256;
            int r = seg >> 2;
            int cf = (seg & 3) * 4;
            int gr = row0 + r;
            int grc = gr < M ? gr : (M - 1);
            cp_async16(&As[buf][r][cf],
                       A + (size_t)grc * K + k0 + cf,
                       gr < M ? 16 : 0);
        }
        {
            int r = tid >> 4;
            int cf = (tid & 15) * 4;
            cp_async16(&Bs[buf][r][cf],
                       B + (size_t)(k0 + r) * Nc + col0 + cf, 16);
        }
    };

    auto compute = [&](int buf) {
        #pragma unroll
        for (int ks = 0; ks < 16; ks += 8) {
            uint32_t af[2][4], bf[4][2];
            #pragma unroll
            for (int tm = 0; tm < 2; tm++) {
                int mrow = warp_m * 32 + tm * 16 + gid;
                af[tm][0] = f2tf(As[buf][mrow][ks + tig]);
                af[tm][1] = f2tf(As[buf][mrow + 8][ks + tig]);
                af[tm][2] = f2tf(As[buf][mrow][ks + tig + 4]);
                af[tm][3] = f2tf(As[buf][mrow + 8][ks + tig + 4]);
            }
            #pragma unroll
            for (int tn = 0; tn < 4; tn++) {
                int ncol = warp_n * 32 + tn * 8 + gid;
                bf[tn][0] = f2tf(Bs[buf][ks + tig][ncol]);
                bf[tn][1] = f2tf(Bs[buf][ks + tig + 4][ncol]);
            }
            #pragma unroll
            for (int tm = 0; tm < 2; tm++)
                #pragma unroll
                for (int tn = 0; tn < 4; tn++)
                    mma_tf32(c[tm][tn][0], c[tm][tn][1], c[tm][tn][2], c[tm][tn][3],
                             af[tm][0], af[tm][1], af[tm][2], af[tm][3],
                             bf[tn][0], bf[tn][1]);
        }
    };

    const int KT = K >> 4;
    load_tile(0, 0);
    CP_COMMIT();
    for (int kt = 0; kt < KT; kt++) {
        int buf = kt & 1;
        if (kt + 1 < KT) {
            load_tile(kt + 1, buf ^ 1);
            CP_COMMIT();
            CP_WAIT1();
        } else {
            CP_WAIT0();
        }
        __syncthreads();
        compute(buf);
        __syncthreads();
    }

    // Epilogue
    #pragma unroll
    for (int tm = 0; tm < 2; tm++) {
        int rbase = row0 + warp_m * 32 + tm * 16 + gid;
        #pragma unroll
        for (int tn = 0; tn < 4; tn++) {
            int gc = col0 + warp_n * 32 + tn * 8 + 2 * tig;
            float bx = 0.f, by = 0.f;
            if (HAS_BIAS) { bx = bias[gc]; by = bias[gc + 1]; }
            #pragma unroll
            for (int half = 0; half < 2; half++) {
                int gr = rbase + half * 8;
                if (gr >= M) continue;
                float v0 = c[tm][tn][half * 2 + 0] + bx;
                float v1 = c[tm][tn][half * 2 + 1] + by;
                if (ACT) { v0 = leaky01(v0); v1 = leaky01(v1); }
                *(float2*)(C + (size_t)gr * ldc + coff + gc) = make_float2(v0, v1);
            }
        }
    }
}

// ---------------------------------------------------------------------------
// num/cat feature linears (K=4, K=3) -> concat columns [128:256), [256:384)
// ---------------------------------------------------------------------------
__global__ void numcat_kernel(
    const float* __restrict__ np_, const float* __restrict__ cp,
    const float* __restrict__ Wn, const float* __restrict__ bn,
    const float* __restrict__ Wc, const float* __restrict__ bc, int N)
{
    int i = blockIdx.x * blockDim.x + threadIdx.x;
    int node = i >> 7;
    int col = i & 127;
    if (node >= N) return;

    float s = bn[col];
    #pragma unroll
    for (int k = 0; k < 4; k++) s += np_[node * 4 + k] * Wn[k * 128 + col];
    g_bufA[(size_t)node * EMB + 128 + col] = leaky01(s);

    float t = bc[col];
    #pragma unroll
    for (int k = 0; k < 3; k++) t += cp[node * 3 + k] * Wc[k * 128 + col];
    g_bufA[(size_t)node * EMB + 256 + col] = leaky01(t);
}

// ---------------------------------------------------------------------------
// Degree / dinv / CSR build (edge_index int32; CSR keyed by dst, stores src)
// ---------------------------------------------------------------------------
__global__ void zero_deg(int N)
{
    int i = blockIdx.x * blockDim.x + threadIdx.x;
    if (i < N) g_deg[i] = 0;
}

__global__ void count_deg(const int* __restrict__ ei, int E)
{
    int e = blockIdx.x * blockDim.x + threadIdx.x;
    if (e < E) atomicAdd(&g_deg[ei[E + e]], 1);
}

// Pass 1: per-block sums of deg (256 elems/block) + dinv
__global__ void scan_pass1(int N)
{
    __shared__ int red[256];
    int t = threadIdx.x;
    int i = blockIdx.x * 256 + t;
    int d = (i < N) ? g_deg[i] : 0;
    if (i < N) g_dinv[i] = rsqrtf((float)d + 1.0f);
    red[t] = d;
    __syncthreads();
    #pragma unroll
    for (int off = 128; off > 0; off >>= 1) {
        if (t < off) red[t] += red[t + off];
        __syncthreads();
    }
    if (t == 0) g_bsum[blockIdx.x] = red[0];
}

// Pass 2: single block exclusive-scans the <=1024 block sums in place
__global__ void __launch_bounds__(1024) scan_pass2(int NB)
{
    __shared__ int s[1024];
    int t = threadIdx.x;
    int v = (t < NB) ? g_bsum[t] : 0;
    s[t] = v;
    __syncthreads();
    #pragma unroll
    for (int off = 1; off < 1024; off <<= 1) {
        int u = (t >= off) ? s[t - off] : 0;
        __syncthreads();
        s[t] += u;
        __syncthreads();
    }
    if (t < NB) g_bsum[t] = s[t] - v;   // exclusive
}

// Pass 3: per-block local exclusive scan + base -> rowptr; zero cnt
__global__ void scan_pass3(int N)
{
    __shared__ int s[256];
    int t = threadIdx.x;
    int i = blockIdx.x * 256 + t;
    int d = (i < N) ? g_deg[i] : 0;
    s[t] = d;
    __syncthreads();
    #pragma unroll
    for (int off = 1; off < 256; off <<= 1) {
        int u = (t >= off) ? s[t - off] : 0;
        __syncthreads();
        s[t] += u;
        __syncthreads();
    }
    int base = g_bsum[blockIdx.x];
    if (i < N) {
        g_rowptr[i] = base + s[t] - d;   // exclusive
        g_cnt[i] = 0;
        if (i == N - 1) g_rowptr[N] = base + s[t];
    }
}

__global__ void fill_csr(const int* __restrict__ ei, int E)
{
    int e = blockIdx.x * blockDim.x + threadIdx.x;
    if (e >= E) return;
    int d = ei[E + e];
    int pos = g_rowptr[d] + atomicAdd(&g_cnt[d], 1);
    g_csr[pos] = ei[e];
}

// ---------------------------------------------------------------------------
// GCN gather: one warp per node, 4-edge unrolled for MLP.
// agg[n] = sum_{s in in(n)} xw[s]*dinv[s]*dinv[n] + xw[n]*dinv[n]^2 + bias
// ---------------------------------------------------------------------------
__device__ __forceinline__ void fma4(float4& a, const float4 v, float n) {
    a.x = fmaf(v.x, n, a.x);
    a.y = fmaf(v.y, n, a.y);
    a.z = fmaf(v.z, n, a.z);
    a.w = fmaf(v.w, n, a.w);
}

template <int SRC, int DST>
__global__ void gcn_gather(const float* __restrict__ bias, int N)
{
    const float* __restrict__ xw = BUF<SRC>();
    float* __restrict__ agg = BUF<DST>();

    int w = (blockIdx.x * blockDim.x + threadIdx.x) >> 5;
    int lane = threadIdx.x & 31;
    if (w >= N) return;

    float din = g_dinv[w];
    float self = din * din;

    const float4* xr = (const float4*)(xw + (size_t)w * EMB);
    const float4* bi = (const float4*)bias;

    float4 a0 = bi[lane], a1 = bi[lane + 32], a2 = bi[lane + 64];
    fma4(a0, xr[lane], self);
    fma4(a1, xr[lane + 32], self);
    fma4(a2, xr[lane + 64], self);

    int p = g_rowptr[w];
    const int pe = g_rowptr[w + 1];

    for (; p + 3 < pe; p += 4) {
        int s0 = g_csr[p], s1 = g_csr[p + 1], s2 = g_csr[p + 2], s3 = g_csr[p + 3];
        float n0 = g_dinv[s0] * din;
        float n1 = g_dinv[s1] * din;
        float n2 = g_dinv[s2] * din;
        float n3 = g_dinv[s3] * din;
        const float4* x0 = (const float4*)(xw + (size_t)s0 * EMB);
        const float4* x1 = (const float4*)(xw + (size_t)s1 * EMB);
        const float4* x2 = (const float4*)(xw + (size_t)s2 * EMB);
        const float4* x3 = (const float4*)(xw + (size_t)s3 * EMB);
        float4 v00 = x0[lane], v01 = x0[lane + 32], v02 = x0[lane + 64];
        float4 v10 = x1[lane], v11 = x1[lane + 32], v12 = x1[lane + 64];
        float4 v20 = x2[lane], v21 = x2[lane + 32], v22 = x2[lane + 64];
        float4 v30 = x3[lane], v31 = x3[lane + 32], v32 = x3[lane + 64];
        fma4(a0, v00, n0); fma4(a1, v01, n0); fma4(a2, v02, n0);
        fma4(a0, v10, n1); fma4(a1, v11, n1); fma4(a2, v12, n1);
        fma4(a0, v20, n2); fma4(a1, v21, n2); fma4(a2, v22, n2);
        fma4(a0, v30, n3); fma4(a1, v31, n3); fma4(a2, v32, n3);
    }
    for (; p < pe; p++) {
        int s0 = g_csr[p];
        float n0 = g_dinv[s0] * din;
        const float4* x0 = (const float4*)(xw + (size_t)s0 * EMB);
        fma4(a0, x0[lane], n0);
        fma4(a1, x0[lane + 32], n0);
        fma4(a2, x0[lane + 64], n0);
    }

    float4* ar = (float4*)(agg + (size_t)w * EMB);
    ar[lane] = a0;
    ar[lane + 32] = a1;
    ar[lane + 64] = a2;
}

// ---------------------------------------------------------------------------
// Final projection to 2 logits from g_bufA: one warp per node.
// ---------------------------------------------------------------------------
__global__ void out_kernel(
    const float* __restrict__ W, const float* __restrict__ b,
    float* __restrict__ out, int N)
{
    int warp = (blockIdx.x * blockDim.x + threadIdx.x) >> 5;
    int lane = threadIdx.x & 31;
    if (warp >= N) return;

    const float* x = g_bufA + (size_t)warp * EMB;
    float s0 = 0.f, s1 = 0.f;
    #pragma unroll
    for (int it = 0; it < EMB / 32; it++) {
        int j = it * 32 + lane;
        float v = x[j];
        s0 += v * W[j * 2 + 0];
        s1 += v * W[j * 2 + 1];
    }
    #pragma unroll
    for (int o = 16; o > 0; o >>= 1) {
        s0 += __shfl_down_sync(0xFFFFFFFFu, s0, o);
        s1 += __shfl_down_sync(0xFFFFFFFFu, s1, o);
    }
    if (lane == 0) {
        out[(size_t)warp * 2 + 0] = s0 + b[0];
        out[(size_t)warp * 2 + 1] = s1 + b[1];
    }
}

// ---------------------------------------------------------------------------
// Launcher — kernel launches only (graph-capturable, allocation-free)
// ---------------------------------------------------------------------------
extern "C" void kernel_launch(void* const* d_in, const int* in_sizes, int n_in,
                              void* d_out, int out_size)
{
    const float* des = (const float*)d_in[0];
    // d_in[1] = tweet — unused by the reference model
    const float* np_ = (const float*)d_in[2];
    const float* cp  = (const float*)d_in[3];
    const int*   ei  = (const int*)d_in[4];
    const float* W_des = (const float*)d_in[5];  const float* b_des = (const float*)d_in[6];
    const float* W_num = (const float*)d_in[7];  const float* b_num = (const float*)d_in[8];
    const float* W_cat = (const float*)d_in[9];  const float* b_cat = (const float*)d_in[10];
    const float* W_in  = (const float*)d_in[11]; const float* b_in  = (const float*)d_in[12];
    const float* W_g1  = (const float*)d_in[13]; const float* b_g1  = (const float*)d_in[14];
    const float* W_g2  = (const float*)d_in[15]; const float* b_g2  = (const float*)d_in[16];
    const float* W_o1  = (const float*)d_in[17]; const float* b_o1  = (const float*)d_in[18];
    const float* W_o2  = (const float*)d_in[19]; const float* b_o2  = (const float*)d_in[20];

    const int N = in_sizes[0] / 768;
    const int E = in_sizes[4] / 2;

    const int mb = (N + 127) / 128;
    const int NB = (N + 255) / 256;
    const int nwarpgrid = (int)(((size_t)N * 32 + 255) / 256);

    // --- degree / dinv / CSR ---
    zero_deg<<<NB, 256>>>(N);
    count_deg<<<(E + 255) / 256, 256>>>(ei, E);
    scan_pass1<<<NB, 256>>>(N);
    scan_pass2<<<1, 1024>>>(NB);
    scan_pass3<<<NB, 256>>>(N);
    fill_csr<<<(E + 255) / 256, 256>>>(ei, E);

    // --- feature embedding: bufA = concat of 3 leaky-linears ---
    tgemm<-1, 0, 1, 1><<<dim3(2, mb), 256>>>(des, W_des, b_des, N, 768, 128, EMB, 0);
    numcat_kernel<<<(N * 128 + 255) / 256, 256>>>(np_, cp, W_num, b_num, W_cat, b_cat, N);

    // --- input linear: bufB = leaky(bufA @ W_in + b_in) ---
    tgemm<0, 1, 1, 1><<<dim3(6, mb), 256>>>(nullptr, W_in, b_in, N, EMB, EMB, EMB, 0);

    // --- GCN conv 1: bufC = bufB @ W_g1 ; bufA = gather(bufC) + b_g1 ---
    tgemm<1, 2, 0, 0><<<dim3(6, mb), 256>>>(nullptr, W_g1, nullptr, N, EMB, EMB, EMB, 0);
    gcn_gather<2, 0><<<nwarpgrid, 256>>>(b_g1, N);

    // --- GCN conv 2: bufC = bufA @ W_g2 ; bufB = gather(bufC) + b_g2 ---
    tgemm<0, 2, 0, 0><<<dim3(6, mb), 256>>>(nullptr, W_g2, nullptr, N, EMB, EMB, EMB, 0);
    gcn_gather<2, 1><<<nwarpgrid, 256>>>(b_g2, N);

    // --- output head: bufA = leaky(bufB @ W_o1 + b_o1); out = bufA @ W_o2 + b_o2 ---
    tgemm<1, 0, 1, 1><<<dim3(6, mb), 256>>>(nullptr, W_o1, b_o1, N, EMB, EMB, EMB, 0);
    out_kernel<<<nwarpgrid, 256>>>(W_o2, b_o2, (float*)d_out, N);
}

// round 7
// speedup vs baseline: 1.2360x; 1.1120x over previous
#include <cuda_runtime.h>
#include <cuda_fp16.h>
#include <cstddef>
#include <cstdint>

#define EMB 384
#define NMAX 50000
#define EMAX 800000

// Scratch (static __device__ arrays; no allocation anywhere)
__device__ float  g_bufA[(size_t)NMAX * EMB];
__device__ float  g_bufB[(size_t)NMAX * EMB];
__device__ __half g_bufH[(size_t)NMAX * EMB];
__device__ float  g_dinv[NMAX];
__device__ int    g_deg[NMAX];
__device__ int    g_rowptr[NMAX + 1];
__device__ int    g_cnt[NMAX];
__device__ int    g_csr[EMAX];
__device__ int    g_bsum[1024];

template <int SEL>
__device__ __forceinline__ float* BUF() {
    if constexpr (SEL == 0) return g_bufA;
    else return g_bufB;
}

__device__ __forceinline__ float leaky01(float x) { return x > 0.f ? x : 0.01f * x; }

__device__ __forceinline__ uint32_t f2tf(float x) {
    uint32_t u;
    asm("cvt.rna.tf32.f32 %0, %1;" : "=r"(u) : "f"(x));
    return u;
}

__device__ __forceinline__ void cp_async16(void* smem_dst, const void* gsrc, int src_bytes) {
    uint32_t saddr = (uint32_t)__cvta_generic_to_shared(smem_dst);
    asm volatile("cp.async.cg.shared.global [%0], [%1], 16, %2;"
                 :: "r"(saddr), "l"(gsrc), "r"(src_bytes) : "memory");
}
#define CP_COMMIT() asm volatile("cp.async.commit_group;" ::: "memory")
#define CP_WAIT1()  asm volatile("cp.async.wait_group 1;" ::: "memory")
#define CP_WAIT0()  asm volatile("cp.async.wait_group 0;" ::: "memory")

__device__ __forceinline__ void mma_tf32(
    float& c0, float& c1, float& c2, float& c3,
    uint32_t a0, uint32_t a1, uint32_t a2, uint32_t a3,
    uint32_t b0, uint32_t b1)
{
    asm volatile(
        "mma.sync.aligned.m16n8k8.row.col.f32.tf32.tf32.f32 "
        "{%0,%1,%2,%3}, {%4,%5,%6,%7}, {%8,%9}, {%0,%1,%2,%3};"
        : "+f"(c0), "+f"(c1), "+f"(c2), "+f"(c3)
        : "r"(a0), "r"(a1), "r"(a2), "r"(a3), "r"(b0), "r"(b1));
}

// ---------------------------------------------------------------------------
// tf32 tensor-core GEMM, cp.async double-buffered (R4-proven core).
// BM=128, BN=64, BK=16, 2 stages. 8 warps: 4(m) x 2(n), warp tile 32x32.
// HALF_OUT: C -> g_bufH (fp16). FUSE_OUT: epilogue dots with W2 (384x2) and
// atomically accumulates 2 logits/row into outp (pre-initialized with bias).
// ---------------------------------------------------------------------------
template <int SRC, int DST, int HAS_BIAS, int ACT, int HALF_OUT, int FUSE_OUT>
__global__ void __launch_bounds__(256) tgemm(
    const float* __restrict__ Ain, const float* __restrict__ B,
    const float* __restrict__ bias,
    const float* __restrict__ W2, float* __restrict__ outp,
    int M, int K, int Nc, int ldc, int coff)
{
    const float* __restrict__ A;
    if constexpr (SRC < 0) A = Ain; else A = BUF<SRC>();

    __shared__ float As[2][128][20];
    __shared__ float Bs[2][16][72];
    __shared__ float Wo[64][2];

    const int tid = threadIdx.x;
    const int lane = tid & 31;
    const int warp = tid >> 5;
    const int warp_m = warp & 3;
    const int warp_n = warp >> 2;
    const int gid = lane >> 2;
    const int tig = lane & 3;

    const int row0 = blockIdx.y * 128;
    const int col0 = blockIdx.x * 64;

    if constexpr (FUSE_OUT) {
        if (tid < 64) {
            Wo[tid][0] = W2[(col0 + tid) * 2 + 0];
            Wo[tid][1] = W2[(col0 + tid) * 2 + 1];
        }
    }

    float c[2][4][4];
    #pragma unroll
    for (int i = 0; i < 2; i++)
        #pragma unroll
        for (int j = 0; j < 4; j++)
            #pragma unroll
            for (int q = 0; q < 4; q++) c[i][j][q] = 0.f;

    auto load_tile = [&](int kt, int buf) {
        const int k0 = kt * 16;
        #pragma unroll
        for (int i = 0; i < 2; i++) {
            int seg = tid + i * 256;
            int r = seg >> 2;
            int cf = (seg & 3) * 4;
            int gr = row0 + r;
            int grc = gr < M ? gr : (M - 1);
            cp_async16(&As[buf][r][cf],
                       A + (size_t)grc * K + k0 + cf,
                       gr < M ? 16 : 0);
        }
        {
            int r = tid >> 4;
            int cf = (tid & 15) * 4;
            cp_async16(&Bs[buf][r][cf],
                       B + (size_t)(k0 + r) * Nc + col0 + cf, 16);
        }
    };

    auto compute = [&](int buf) {
        #pragma unroll
        for (int ks = 0; ks < 16; ks += 8) {
            uint32_t af[2][4], bf[4][2];
            #pragma unroll
            for (int tm = 0; tm < 2; tm++) {
                int mrow = warp_m * 32 + tm * 16 + gid;
                af[tm][0] = f2tf(As[buf][mrow][ks + tig]);
                af[tm][1] = f2tf(As[buf][mrow + 8][ks + tig]);
                af[tm][2] = f2tf(As[buf][mrow][ks + tig + 4]);
                af[tm][3] = f2tf(As[buf][mrow + 8][ks + tig + 4]);
            }
            #pragma unroll
            for (int tn = 0; tn < 4; tn++) {
                int ncol = warp_n * 32 + tn * 8 + gid;
                bf[tn][0] = f2tf(Bs[buf][ks + tig][ncol]);
                bf[tn][1] = f2tf(Bs[buf][ks + tig + 4][ncol]);
            }
            #pragma unroll
            for (int tm = 0; tm < 2; tm++)
                #pragma unroll
                for (int tn = 0; tn < 4; tn++)
                    mma_tf32(c[tm][tn][0], c[tm][tn][1], c[tm][tn][2], c[tm][tn][3],
                             af[tm][0], af[tm][1], af[tm][2], af[tm][3],
                             bf[tn][0], bf[tn][1]);
        }
    };

    const int KT = K >> 4;
    load_tile(0, 0);
    CP_COMMIT();
    for (int kt = 0; kt < KT; kt++) {
        int buf = kt & 1;
        if (kt + 1 < KT) {
            load_tile(kt + 1, buf ^ 1);
            CP_COMMIT();
            CP_WAIT1();
        } else {
            CP_WAIT0();
        }
        __syncthreads();
        compute(buf);
        __syncthreads();
    }

    // Epilogue
    if constexpr (FUSE_OUT) {
        #pragma unroll
        for (int tm = 0; tm < 2; tm++) {
            #pragma unroll
            for (int half_i = 0; half_i < 2; half_i++) {
                int gr = row0 + warp_m * 32 + tm * 16 + gid + half_i * 8;
                float s0 = 0.f, s1 = 0.f;
                #pragma unroll
                for (int tn = 0; tn < 4; tn++) {
                    int lc = warp_n * 32 + tn * 8 + 2 * tig;
                    float v0 = c[tm][tn][half_i * 2 + 0];
                    float v1 = c[tm][tn][half_i * 2 + 1];
                    if (HAS_BIAS) { v0 += bias[col0 + lc]; v1 += bias[col0 + lc + 1]; }
                    if (ACT) { v0 = leaky01(v0); v1 = leaky01(v1); }
                    s0 += v0 * Wo[lc][0] + v1 * Wo[lc + 1][0];
                    s1 += v0 * Wo[lc][1] + v1 * Wo[lc + 1][1];
                }
                // reduce across the 4-lane quad (tig 0..3 are consecutive lanes)
                s0 += __shfl_down_sync(0xFFFFFFFFu, s0, 1, 4);
                s0 += __shfl_down_sync(0xFFFFFFFFu, s0, 2, 4);
                s1 += __shfl_down_sync(0xFFFFFFFFu, s1, 1, 4);
                s1 += __shfl_down_sync(0xFFFFFFFFu, s1, 2, 4);
                if (tig == 0 && gr < M) {
                    atomicAdd(outp + (size_t)gr * 2 + 0, s0);
                    atomicAdd(outp + (size_t)gr * 2 + 1, s1);
                }
            }
        }
    } else {
        #pragma unroll
        for (int tm = 0; tm < 2; tm++) {
            int rbase = row0 + warp_m * 32 + tm * 16 + gid;
            #pragma unroll
            for (int tn = 0; tn < 4; tn++) {
                int gc = col0 + warp_n * 32 + tn * 8 + 2 * tig;
                float bx = 0.f, by = 0.f;
                if (HAS_BIAS) { bx = bias[gc]; by = bias[gc + 1]; }
                #pragma unroll
                for (int half_i = 0; half_i < 2; half_i++) {
                    int gr = rbase + half_i * 8;
                    if (gr >= M) continue;
                    float v0 = c[tm][tn][half_i * 2 + 0] + bx;
                    float v1 = c[tm][tn][half_i * 2 + 1] + by;
                    if (ACT) { v0 = leaky01(v0); v1 = leaky01(v1); }
                    if constexpr (HALF_OUT) {
                        *(half2*)(g_bufH + (size_t)gr * ldc + coff + gc) =
                            __floats2half2_rn(v0, v1);
                    } else {
                        *(float2*)(BUF<DST>() + (size_t)gr * ldc + coff + gc) =
                            make_float2(v0, v1);
                    }
                }
            }
        }
    }
}

// ---------------------------------------------------------------------------
// num/cat feature linears (K=4, K=3) -> concat columns [128:256), [256:384)
// ---------------------------------------------------------------------------
__global__ void numcat_kernel(
    const float* __restrict__ np_, const float* __restrict__ cp,
    const float* __restrict__ Wn, const float* __restrict__ bn,
    const float* __restrict__ Wc, const float* __restrict__ bc, int N)
{
    int i = blockIdx.x * blockDim.x + threadIdx.x;
    int node = i >> 7;
    int col = i & 127;
    if (node >= N) return;

    float s = bn[col];
    #pragma unroll
    for (int k = 0; k < 4; k++) s += np_[node * 4 + k] * Wn[k * 128 + col];
    g_bufA[(size_t)node * EMB + 128 + col] = leaky01(s);

    float t = bc[col];
    #pragma unroll
    for (int k = 0; k < 3; k++) t += cp[node * 3 + k] * Wc[k * 128 + col];
    g_bufA[(size_t)node * EMB + 256 + col] = leaky01(t);
}

// ---------------------------------------------------------------------------
// Degree / dinv / CSR build
// ---------------------------------------------------------------------------
__global__ void zero_deg(int N)
{
    int i = blockIdx.x * blockDim.x + threadIdx.x;
    if (i < N) g_deg[i] = 0;
}

__global__ void count_deg(const int* __restrict__ ei, int E)
{
    int e = blockIdx.x * blockDim.x + threadIdx.x;
    if (e < E) atomicAdd(&g_deg[ei[E + e]], 1);
}

__global__ void scan_pass1(int N)
{
    __shared__ int red[256];
    int t = threadIdx.x;
    int i = blockIdx.x * 256 + t;
    int d = (i < N) ? g_deg[i] : 0;
    if (i < N) g_dinv[i] = rsqrtf((float)d + 1.0f);
    red[t] = d;
    __syncthreads();
    #pragma unroll
    for (int off = 128; off > 0; off >>= 1) {
        if (t < off) red[t] += red[t + off];
        __syncthreads();
    }
    if (t == 0) g_bsum[blockIdx.x] = red[0];
}

__global__ void __launch_bounds__(1024) scan_pass2(int NB)
{
    __shared__ int s[1024];
    int t = threadIdx.x;
    int v = (t < NB) ? g_bsum[t] : 0;
    s[t] = v;
    __syncthreads();
    #pragma unroll
    for (int off = 1; off < 1024; off <<= 1) {
        int u = (t >= off) ? s[t - off] : 0;
        __syncthreads();
        s[t] += u;
        __syncthreads();
    }
    if (t < NB) g_bsum[t] = s[t] - v;
}

__global__ void scan_pass3(int N)
{
    __shared__ int s[256];
    int t = threadIdx.x;
    int i = blockIdx.x * 256 + t;
    int d = (i < N) ? g_deg[i] : 0;
    s[t] = d;
    __syncthreads();
    #pragma unroll
    for (int off = 1; off < 256; off <<= 1) {
        int u = (t >= off) ? s[t - off] : 0;
        __syncthreads();
        s[t] += u;
        __syncthreads();
    }
    int base = g_bsum[blockIdx.x];
    if (i < N) {
        g_rowptr[i] = base + s[t] - d;
        g_cnt[i] = 0;
        if (i == N - 1) g_rowptr[N] = base + s[t];
    }
}

__global__ void fill_csr(const int* __restrict__ ei, int E)
{
    int e = blockIdx.x * blockDim.x + threadIdx.x;
    if (e >= E) return;
    int d = ei[E + e];
    int pos = g_rowptr[d] + atomicAdd(&g_cnt[d], 1);
    g_csr[pos] = ei[e];
}

// ---------------------------------------------------------------------------
// GCN gather from fp16 messages: one warp per node, 4-edge unrolled.
// agg[n] = sum_{s in in(n)} h[s]*dinv[s]*dinv[n] + h[n]*dinv[n]^2 + bias
// Row = 384 halves = 96 uint2; lane j handles halves [4j..4j+3] (+128, +256).
// ---------------------------------------------------------------------------
__device__ __forceinline__ void fmah(float4& a, const uint2 u, float n) {
    const half2* h = (const half2*)&u;
    float2 f0 = __half22float2(h[0]);
    float2 f1 = __half22float2(h[1]);
    a.x = fmaf(f0.x, n, a.x);
    a.y = fmaf(f0.y, n, a.y);
    a.z = fmaf(f1.x, n, a.z);
    a.w = fmaf(f1.y, n, a.w);
}

template <int DST>
__global__ void gcn_gather_h(const float* __restrict__ bias, int N)
{
    const __half* __restrict__ xw = g_bufH;
    float* __restrict__ agg = BUF<DST>();

    int w = (blockIdx.x * blockDim.x + threadIdx.x) >> 5;
    int lane = threadIdx.x & 31;
    if (w >= N) return;

    float din = g_dinv[w];
    float self = din * din;

    const uint2* xr = (const uint2*)(xw + (size_t)w * EMB);
    const float4* bi = (const float4*)bias;

    float4 a0 = bi[lane], a1 = bi[lane + 32], a2 = bi[lane + 64];
    fmah(a0, xr[lane], self);
    fmah(a1, xr[lane + 32], self);
    fmah(a2, xr[lane + 64], self);

    int p = g_rowptr[w];
    const int pe = g_rowptr[w + 1];

    for (; p + 3 < pe; p += 4) {
        int s0 = g_csr[p], s1 = g_csr[p + 1], s2 = g_csr[p + 2], s3 = g_csr[p + 3];
        float n0 = g_dinv[s0] * din;
        float n1 = g_dinv[s1] * din;
        float n2 = g_dinv[s2] * din;
        float n3 = g_dinv[s3] * din;
        const uint2* x0 = (const uint2*)(xw + (size_t)s0 * EMB);
        const uint2* x1 = (const uint2*)(xw + (size_t)s1 * EMB);
        const uint2* x2 = (const uint2*)(xw + (size_t)s2 * EMB);
        const uint2* x3 = (const uint2*)(xw + (size_t)s3 * EMB);
        uint2 v00 = x0[lane], v01 = x0[lane + 32], v02 = x0[lane + 64];
        uint2 v10 = x1[lane], v11 = x1[lane + 32], v12 = x1[lane + 64];
        uint2 v20 = x2[lane], v21 = x2[lane + 32], v22 = x2[lane + 64];
        uint2 v30 = x3[lane], v31 = x3[lane + 32], v32 = x3[lane + 64];
        fmah(a0, v00, n0); fmah(a1, v01, n0); fmah(a2, v02, n0);
        fmah(a0, v10, n1); fmah(a1, v11, n1); fmah(a2, v12, n1);
        fmah(a0, v20, n2); fmah(a1, v21, n2); fmah(a2, v22, n2);
        fmah(a0, v30, n3); fmah(a1, v31, n3); fmah(a2, v32, n3);
    }
    for (; p < pe; p++) {
        int s0 = g_csr[p];
        float n0 = g_dinv[s0] * din;
        const uint2* x0 = (const uint2*)(xw + (size_t)s0 * EMB);
        fmah(a0, x0[lane], n0);
        fmah(a1, x0[lane + 32], n0);
        fmah(a2, x0[lane + 64], n0);
    }

    float4* ar = (float4*)(agg + (size_t)w * EMB);
    ar[lane] = a0;
    ar[lane + 32] = a1;
    ar[lane + 64] = a2;
}

// ---------------------------------------------------------------------------
// Initialize output with bias (FUSE_OUT epilogue accumulates on top)
// ---------------------------------------------------------------------------
__global__ void init_out(float* __restrict__ out, const float* __restrict__ b, int N)
{
    int i = blockIdx.x * blockDim.x + threadIdx.x;
    if (i < N) {
        out[(size_t)i * 2 + 0] = b[0];
        out[(size_t)i * 2 + 1] = b[1];
    }
}

// ---------------------------------------------------------------------------
// Launcher — kernel launches only (graph-capturable, allocation-free)
// ---------------------------------------------------------------------------
extern "C" void kernel_launch(void* const* d_in, const int* in_sizes, int n_in,
                              void* d_out, int out_size)
{
    const float* des = (const float*)d_in[0];
    // d_in[1] = tweet — unused by the reference model
    const float* np_ = (const float*)d_in[2];
    const float* cp  = (const float*)d_in[3];
    const int*   ei  = (const int*)d_in[4];
    const float* W_des = (const float*)d_in[5];  const float* b_des = (const float*)d_in[6];
    const float* W_num = (const float*)d_in[7];  const float* b_num = (const float*)d_in[8];
    const float* W_cat = (const float*)d_in[9];  const float* b_cat = (const float*)d_in[10];
    const float* W_in  = (const float*)d_in[11]; const float* b_in  = (const float*)d_in[12];
    const float* W_g1  = (const float*)d_in[13]; const float* b_g1  = (const float*)d_in[14];
    const float* W_g2  = (const float*)d_in[15]; const float* b_g2  = (const float*)d_in[16];
    const float* W_o1  = (const float*)d_in[17]; const float* b_o1  = (const float*)d_in[18];
    const float* W_o2  = (const float*)d_in[19]; const float* b_o2  = (const float*)d_in[20];

    const int N = in_sizes[0] / 768;
    const int E = in_sizes[4] / 2;
    float* out = (float*)d_out;

    const int mb = (N + 127) / 128;
    const int NB = (N + 255) / 256;
    const int nwarpgrid = (int)(((size_t)N * 32 + 255) / 256);

    // --- degree / dinv / CSR ---
    zero_deg<<<NB, 256>>>(N);
    count_deg<<<(E + 255) / 256, 256>>>(ei, E);
    scan_pass1<<<NB, 256>>>(N);
    scan_pass2<<<1, 1024>>>(NB);
    scan_pass3<<<NB, 256>>>(N);
    fill_csr<<<(E + 255) / 256, 256>>>(ei, E);

    // --- feature embedding: bufA = concat of 3 leaky-linears ---
    tgemm<-1, 0, 1, 1, 0, 0><<<dim3(2, mb), 256>>>(des, W_des, b_des, nullptr, nullptr,
                                                   N, 768, 128, EMB, 0);
    numcat_kernel<<<(N * 128 + 255) / 256, 256>>>(np_, cp, W_num, b_num, W_cat, b_cat, N);

    // --- input linear: bufB = leaky(bufA @ W_in + b_in) ---
    tgemm<0, 1, 1, 1, 0, 0><<<dim3(6, mb), 256>>>(nullptr, W_in, b_in, nullptr, nullptr,
                                                  N, EMB, EMB, EMB, 0);

    // --- GCN conv 1: bufH = fp16(bufB @ W_g1) ; bufA = gather(bufH) + b_g1 ---
    tgemm<1, 0, 0, 0, 1, 0><<<dim3(6, mb), 256>>>(nullptr, W_g1, nullptr, nullptr, nullptr,
                                                  N, EMB, EMB, EMB, 0);
    gcn_gather_h<0><<<nwarpgrid, 256>>>(b_g1, N);

    // --- GCN conv 2: bufH = fp16(bufA @ W_g2) ; bufB = gather(bufH) + b_g2 ---
    tgemm<0, 0, 0, 0, 1, 0><<<dim3(6, mb), 256>>>(nullptr, W_g2, nullptr, nullptr, nullptr,
                                                  N, EMB, EMB, EMB, 0);
    gcn_gather_h<1><<<nwarpgrid, 256>>>(b_g2, N);

    // --- output head fused: out = leaky(bufB @ W_o1 + b_o1) @ W_o2 + b_o2 ---
    init_out<<<NB, 256>>>(out, b_o2, N);
    tgemm<1, 0, 1, 1, 0, 1><<<dim3(6, mb), 256>>>(nullptr, W_o1, b_o1, W_o2, out,
                                                  N, EMB, EMB, EMB, 0);
}